// round 1
// baseline (speedup 1.0000x reference)
#include <cuda_runtime.h>
#include <cuda_bf16.h>

// DeepFilter: 5-tap complex FIR over first 256 freq bins + passthrough of the rest.
// spec:  [B=8][2][T=4096][F=481]  fp32
// coefs: [B=8][10][T=4096][256]   fp32   (10 = {real taps 0..4, imag taps 0..4})
// out:   [B=8][2][T=4096][F=481]  fp32
//
// Memory-bound: ~590 MB total traffic. One block per (b,t), 256 threads (= one per
// filtered freq bin). Tail bins 256..480 copied by the same block (450 elems, 2 iters).

#define NUM_FREQS 256
#define FRAME_SIZE 5
#define B_DIM 8
#define T_DIM 4096
#define F_TOTAL 481

__global__ __launch_bounds__(256) void deepfilter_kernel(
    const float* __restrict__ spec,
    const float* __restrict__ coefs,
    float* __restrict__ out)
{
    const int bt = blockIdx.x;          // 0 .. B*T-1
    const int b  = bt / T_DIM;
    const int t  = bt - b * T_DIM;
    const int f  = threadIdx.x;         // 0 .. 255

    // Base offsets
    const long spec_b0 = (long)(b * 2 + 0) * T_DIM * F_TOTAL;   // real channel
    const long spec_b1 = (long)(b * 2 + 1) * T_DIM * F_TOTAL;   // imag channel
    const long coef_bt = ((long)b * 10) * T_DIM * NUM_FREQS + (long)t * NUM_FREQS + f;
    const long coef_k_stride = (long)T_DIM * NUM_FREQS;

    float re = 0.0f, im = 0.0f;

#pragma unroll
    for (int k = 0; k < FRAME_SIZE; ++k) {
        const int ts = t + k - (FRAME_SIZE - 1);   // t + k - 4
        float pr = 0.0f, pi = 0.0f;
        if (ts >= 0) {
            const long so = (long)ts * F_TOTAL + f;
            pr = spec[spec_b0 + so];
            pi = spec[spec_b1 + so];
        }
        const float cr = coefs[coef_bt + (long)k * coef_k_stride];
        const float ci = coefs[coef_bt + (long)(k + FRAME_SIZE) * coef_k_stride];
        re = fmaf(pr, cr, re);
        re = fmaf(-pi, ci, re);
        im = fmaf(pi, cr, im);
        im = fmaf(pr, ci, im);
    }

    const long orow = (long)t * F_TOTAL + f;
    out[spec_b0 + orow] = re;
    out[spec_b1 + orow] = im;

    // Passthrough bins f = 256..480 for both channels: 2*225 = 450 elems per (b,t).
    for (int idx = threadIdx.x; idx < 2 * (F_TOTAL - NUM_FREQS); idx += 256) {
        const int ch = idx / (F_TOTAL - NUM_FREQS);
        const int j  = idx - ch * (F_TOTAL - NUM_FREQS);
        const long o = (long)(b * 2 + ch) * T_DIM * F_TOTAL + (long)t * F_TOTAL + NUM_FREQS + j;
        out[o] = spec[o];
    }
}

extern "C" void kernel_launch(void* const* d_in, const int* in_sizes, int n_in,
                              void* d_out, int out_size)
{
    const float* spec  = (const float*)d_in[0];
    const float* coefs = (const float*)d_in[1];
    float* out = (float*)d_out;

    dim3 grid(B_DIM * T_DIM);
    dim3 block(256);
    deepfilter_kernel<<<grid, block>>>(spec, coefs, out);
}